// round 15
// baseline (speedup 1.0000x reference)
#include <cuda_runtime.h>
#include <math.h>

#define NBLK 128
#define EPSF 1e-8f

// smem layout (dynamic, one CTA/SM):
//   [0     ,32768) Ws   64x128  (A1 h-part weights, loaded once)
//   [32768 ,40960) Xs   64x32   (A1 activations, per step)
//   [40960 ,74240) Ms   128x65  (persistent M, B CTAs)
//   [74240 ,74752) wr   (persistent)
//   [74752 ,75264) ww   (persistent)
//   [75264 ,79360) Wrs  16x64   (persistent r-slice weights)
//   [79360 ,89600) scratch: A2 gs[512]+rsm[2048] | C sred[768] | B2 transients
#define SMEM_BYTES 89600

__device__ float d_XP[256*2048*32];     // [t][row][b]
__device__ float d_XinT[256*256*32];    // [t][i][b]
__device__ float d_WrecT[576*2048];     // [k][row]
__device__ float d_WxT[256*2048];       // [i][row]
__device__ float d_WheadT[512*272];     // [k][o] padded
__device__ float d_WoutT[576*256];      // [k][o]
__device__ float d_Part[8*2048*32];     // [kc][row][b]
__device__ float d_XT[576*32];          // [k][b] 0..511=h, 512..575=r
__device__ float d_cT[512*32];          // [j][b]
__device__ float d_HR[256*576*32];      // [t][k][b]
__device__ float d_P[272*32];           // [o][b]
__device__ unsigned d_barcnt;
__device__ __align__(128) unsigned d_headcnt[32];

__device__ __forceinline__ float sigmf(float x){ return 1.f/(1.f+expf(-x)); }
__device__ __forceinline__ float softplusf(float x){ return fmaxf(x,0.f)+log1pf(expf(-fabsf(x))); }

__device__ __forceinline__ void gridbar(unsigned target){
    __syncthreads();
    __threadfence();
    if(threadIdx.x==0){
        atomicAdd(&d_barcnt,1u);
        while(*(volatile unsigned*)&d_barcnt < target){ __nanosleep(64); }
        __threadfence();
    }
    __syncthreads();
}

__global__ void prep_kernel(const float* __restrict__ W_ih,const float* __restrict__ W_hh,
                            const float* __restrict__ W_head,const float* __restrict__ W_out){
    if(blockIdx.x==0&&threadIdx.x==0){ d_barcnt=0u; d_headcnt[0]=0u; }
    int tid=blockIdx.x*blockDim.x+threadIdx.x, nt=gridDim.x*blockDim.x;
    for(int i=tid;i<576*2048;i+=nt){
        int k=i>>11,row=i&2047;
        d_WrecT[i]=(k<512)?W_hh[row*512+k]:W_ih[row*320+256+(k-512)];
    }
    for(int i=tid;i<256*2048;i+=nt){
        int k=i>>11,row=i&2047;
        d_WxT[i]=W_ih[row*320+k];
    }
    for(int i=tid;i<512*272;i+=nt){
        int j=i/272,o=i%272;
        d_WheadT[i]=(o<268)?W_head[o*512+j]:0.f;
    }
    for(int i=tid;i<576*256;i+=nt){
        int k=i>>8,o=i&255;
        d_WoutT[i]=W_out[o*576+k];
    }
}

__global__ void tin_kernel(const float* __restrict__ x){
    __shared__ float sm[32][33];
    int it=blockIdx.x,t=blockIdx.y;
    int lane=threadIdx.x&31,r=threadIdx.x>>5,i0=it*32;
#pragma unroll
    for(int q=0;q<4;q++){ int b=r+q*8; sm[lane][b]=x[(b*256+t)*256+i0+lane]; }
    __syncthreads();
#pragma unroll
    for(int q=0;q<4;q++){ int i=r+q*8; d_XinT[(t*256+i0+i)*32+lane]=sm[i][lane]; }
}

__global__ __launch_bounds__(256) void xp_gemm_kernel(){
    __shared__ __align__(16) float Ws[64*128];
    __shared__ __align__(16) float Xs[64*32];
    int rb=blockIdx.x,t=blockIdx.y,tid=threadIdx.x;
    int ty=tid>>3,tx=tid&7;
    float acc[4][4]={};
    for(int kc=0;kc<4;kc++){
        for(int idx=tid;idx<64*32;idx+=256){
            int k=idx>>5,r4=idx&31;
            *(float4*)&Ws[k*128+r4*4]=*(const float4*)&d_WxT[(kc*64+k)*2048+rb*128+r4*4];
        }
        for(int idx=tid;idx<64*8;idx+=256){
            int k=idx>>3,b4=idx&7;
            *(float4*)&Xs[k*32+b4*4]=*(const float4*)&d_XinT[(t*256+kc*64+k)*32+b4*4];
        }
        __syncthreads();
#pragma unroll 8
        for(int k=0;k<64;k++){
            float4 wv=*(float4*)&Ws[k*128+ty*4];
            float4 xv=*(float4*)&Xs[k*32+tx*4];
            acc[0][0]+=wv.x*xv.x;acc[0][1]+=wv.x*xv.y;acc[0][2]+=wv.x*xv.z;acc[0][3]+=wv.x*xv.w;
            acc[1][0]+=wv.y*xv.x;acc[1][1]+=wv.y*xv.y;acc[1][2]+=wv.y*xv.z;acc[1][3]+=wv.y*xv.w;
            acc[2][0]+=wv.z*xv.x;acc[2][1]+=wv.z*xv.y;acc[2][2]+=wv.z*xv.z;acc[2][3]+=wv.z*xv.w;
            acc[3][0]+=wv.w*xv.x;acc[3][1]+=wv.w*xv.y;acc[3][2]+=wv.w*xv.z;acc[3][3]+=wv.w*xv.w;
        }
        __syncthreads();
    }
    int row0=rb*128+ty*4;
#pragma unroll
    for(int i=0;i<4;i++)
        *(float4*)&d_XP[(t*2048+row0+i)*32+tx*4]=make_float4(acc[i][0],acc[i][1],acc[i][2],acc[i][3]);
}

__global__ __launch_bounds__(256) void ntm_loop_kernel(const float* __restrict__ b_lstm,
                                                       const float* __restrict__ b_head){
    extern __shared__ __align__(16) char smraw[];
    float* Ws   =(float*)(smraw);           // [64][128]
    float* Xs   =(float*)(smraw+32768);     // [64][32]
    float* Ms   =(float*)(smraw+40960);     // [128][65]
    float* wrp  =(float*)(smraw+74240);
    float* wwp  =(float*)(smraw+74752);
    float* Wrs  =(float*)(smraw+75264);     // [16][64] persistent r-slice
    float* gs   =(float*)(smraw+79360);     // A2: 512
    float* rsm  =(float*)(smraw+81408);     // A2: r staged [c][b] 64x32
    float* sred =(float*)(smraw+79360);     // C/B1 scratch (768)
    float* ps   =(float*)(smraw+79360);     // B2 transients
    float* kr   =ps+272;
    float* kw   =kr+64;
    float* er   =kw+64;
    float* aw   =er+64;
    float* wcr  =aw+64;
    float* wcw  =wcr+128;
    float* redbuf=wcw+128;
    float* sc   =redbuf+8;
    float* minv =sc+16;

    const int g=blockIdx.x,tid=threadIdx.x;
    unsigned nb=0;
    const int rb=g>>3,kc=g&7;
    const int ty=tid>>3,tx=tid&7;
    const bool isB1=(g>=32&&g<122);
    const bool isB2=(g<32);

    // ---- init ----
    {
        int gt=g*256+tid; const int nt=NBLK*256;
        for(int i=gt;i<576*32;i+=nt) d_XT[i]=0.f;
        for(int i=gt;i<512*32;i+=nt) d_cT[i]=0.f;
        for(int i=gt;i<8*2048*32;i+=nt) d_Part[i]=0.f;
    }
    // persistent A1 weights (h-part, k<512), loaded once
    for(int idx=tid;idx<64*32;idx+=256){
        int k=idx>>5,r4=idx&31;
        *(float4*)&Ws[k*128+r4*4]=*(const float4*)&d_WrecT[(kc*64+k)*2048+rb*128+r4*4];
    }
    // persistent r-slice weights
    for(int i=tid;i<1024;i+=256){
        int lr=i>>6,c=i&63;
        int row=(lr>>2)*512 + g*4 + (lr&3);
        Wrs[i]=d_WrecT[(512+c)*2048+row];
    }
    // persistent NTM state for B CTAs
    if(isB2){
        for(int i=tid;i<8192;i+=256) Ms[(i>>6)*65+(i&63)]=0.01f;
        if(tid<128){ float v=(tid==0)?1.f:0.f; wrp[tid]=v; wwp[tid]=v; }
    }
    nb++; gridbar(nb*NBLK);

    for(int t=0;t<256;t++){
        // ===== A2(t): reduce partials + r-part + XP + bias ; LSTM -> h(t) =====
        {
            for(int i=tid;i<512;i+=256)
                *(float4*)&rsm[i*4]=*(const float4*)&d_XT[512*32+i*4];
            __syncthreads();
            for(int v=tid;v<512;v+=256){
                int q=v>>7,jo=(v>>5)&3,b=v&31;
                int row=q*512+g*4+jo;
                int lr=q*4+jo;
                float s=b_lstm[row]+d_XP[(t*2048+row)*32+b];
#pragma unroll
                for(int kk=0;kk<8;kk++) s+=d_Part[(kk*2048+row)*32+b];
#pragma unroll
                for(int c=0;c<64;c+=4){
                    float4 wv=*(const float4*)&Wrs[lr*64+c];
                    s+=wv.x*rsm[c*32+b]+wv.y*rsm[(c+1)*32+b]
                      +wv.z*rsm[(c+2)*32+b]+wv.w*rsm[(c+3)*32+b];
                }
                gs[v]=s;
            }
            __syncthreads();
            if(tid<128){
                int jo=tid>>5,b=tid&31,j=g*4+jo;
                float gi=gs[jo*32+b];
                float gf=gs[128+jo*32+b];
                float gg=gs[256+jo*32+b];
                float go=gs[384+jo*32+b];
                float c=sigmf(gf)*d_cT[j*32+b]+sigmf(gi)*tanhf(gg);
                float h=sigmf(go)*tanhf(c);
                d_cT[j*32+b]=c;
                d_XT[j*32+b]=h;
                d_HR[(t*576+j)*32+b]=h;
            }
            __syncthreads();
        }
        nb++; gridbar(nb*NBLK);

        // ===== C: A1(t+1) h-part partials (all CTAs) + B1(t) head GEMM (g in [32,122)) =====
        {
            for(int idx=tid;idx<64*8;idx+=256){
                int k=idx>>3,b4=idx&7;
                *(float4*)&Xs[k*32+b4*4]=*(const float4*)&d_XT[(kc*64+k)*32+b4*4];
            }
            __syncthreads();
            float acc[4][4]={};
#pragma unroll 4
            for(int k=0;k<64;k++){
                float4 wv=*(float4*)&Ws[k*128+ty*4];
                float4 xv=*(float4*)&Xs[k*32+tx*4];
                acc[0][0]+=wv.x*xv.x;acc[0][1]+=wv.x*xv.y;acc[0][2]+=wv.x*xv.z;acc[0][3]+=wv.x*xv.w;
                acc[1][0]+=wv.y*xv.x;acc[1][1]+=wv.y*xv.y;acc[1][2]+=wv.y*xv.z;acc[1][3]+=wv.y*xv.w;
                acc[2][0]+=wv.z*xv.x;acc[2][1]+=wv.z*xv.y;acc[2][2]+=wv.z*xv.z;acc[2][3]+=wv.z*xv.w;
                acc[3][0]+=wv.w*xv.x;acc[3][1]+=wv.w*xv.y;acc[3][2]+=wv.w*xv.z;acc[3][3]+=wv.w*xv.w;
            }
            int row0=rb*128+ty*4;
#pragma unroll
            for(int i=0;i<4;i++)
                *(float4*)&d_Part[(kc*2048+row0+i)*32+tx*4]=make_float4(acc[i][0],acc[i][1],acc[i][2],acc[i][3]);
            __syncthreads();
        }
        if(isB1){
            int o3=(g-32)*3,kg=tid>>5,b=tid&31;
            float a0=0.f,a1=0.f,a2v=0.f;
            for(int k=kg*64;k<kg*64+64;k++){
                float xv=d_XT[k*32+b];
                a0 +=d_WheadT[k*272+o3  ]*xv;
                a1 +=d_WheadT[k*272+o3+1]*xv;
                a2v+=d_WheadT[k*272+o3+2]*xv;
            }
            sred[kg*96+   b]=a0;
            sred[kg*96+32+b]=a1;
            sred[kg*96+64+b]=a2v;
            __syncthreads();
            if(tid<96){
                int m=tid>>5,bb=tid&31,o=o3+m;
                if(o<268){
                    float s=0.f;
#pragma unroll
                    for(int q=0;q<8;q++) s+=sred[q*96+m*32+bb];
                    d_P[o*32+bb]=s;
                }
            }
            __syncthreads();
            if(tid==0){ __threadfence(); atomicAdd(&d_headcnt[0],1u); }
        }

        // ===== B2(t) (g<32): wait for 90 head producers, then addressing =====
        if(isB2){
            if(tid==0){
                unsigned tgt=90u*(unsigned)(t+1);
                while(*(volatile unsigned*)&d_headcnt[0] < tgt){ __nanosleep(64); }
                __threadfence();
            }
            __syncthreads();
            const int b=g;
            for(int o=tid;o<272;o+=256) ps[o]=(o<268)?(d_P[o*32+b]+b_head[o]):0.f;
            __syncthreads();
            if(tid==0){
                sc[0]=softplusf(ps[64]);
                sc[1]=sigmf(ps[65]);
                float m=fmaxf(ps[66],fmaxf(ps[67],ps[68]));
                float e0=expf(ps[66]-m),e1=expf(ps[67]-m),e2=expf(ps[68]-m);
                float s=e0+e1+e2;
                sc[2]=e0/s;sc[3]=e1/s;sc[4]=e2/s;
                sc[5]=1.f+softplusf(ps[69]);
            }
            if(tid==32){
                sc[6]=softplusf(ps[134]);
                sc[7]=sigmf(ps[135]);
                float m=fmaxf(ps[136],fmaxf(ps[137],ps[138]));
                float e0=expf(ps[136]-m),e1=expf(ps[137]-m),e2=expf(ps[138]-m);
                float s=e0+e1+e2;
                sc[8]=e0/s;sc[9]=e1/s;sc[10]=e2/s;
                sc[11]=1.f+softplusf(ps[139]);
            }
            if(tid==64){
                float s=0.f;
                for(int c=0;c<64;c++){float v=ps[c];s+=v*v;}
                sc[12]=sqrtf(s)+EPSF;
            }
            if(tid==96){
                float s=0.f;
                for(int c=0;c<64;c++){float v=ps[70+c];s+=v*v;}
                sc[13]=sqrtf(s)+EPSF;
            }
            if(tid>=128&&tid<192){
                int c=tid-128;
                kr[c]=ps[c];
                kw[c]=ps[70+c];
                er[c]=sigmf(ps[140+c]);
                aw[c]=ps[204+c];
            }
            __syncthreads();

            const int n=tid&127;
            float myv;
            {
                const float* mr=&Ms[n*65];
                if(tid<128){
                    float m2=0.f,dr=0.f;
                    for(int c=0;c<64;c++){float mv=mr[c];m2+=mv*mv;dr+=mv*kr[c];}
                    float inv=1.f/(sqrtf(m2)+EPSF);
                    minv[n]=inv;
                    myv=sc[0]*dr*inv/sc[12];
                }else{
                    float dw=0.f;
                    for(int c=0;c<64;c++) dw+=mr[c]*kw[c];
                    myv=dw;
                }
            }
            __syncthreads();
            if(tid>=128) myv=sc[6]*myv*minv[n]/sc[13];

            float m=myv;
#pragma unroll
            for(int o=16;o>0;o>>=1) m=fmaxf(m,__shfl_xor_sync(0xffffffffu,m,o));
            if((tid&31)==0) redbuf[tid>>5]=m;
            __syncthreads();
            float h0=fmaxf(fmaxf(redbuf[0],redbuf[1]),fmaxf(redbuf[2],redbuf[3]));
            float h1=fmaxf(fmaxf(redbuf[4],redbuf[5]),fmaxf(redbuf[6],redbuf[7]));
            __syncthreads();
            float ex=expf(myv-((tid<128)?h0:h1));
            float sm2=ex;
#pragma unroll
            for(int o=16;o>0;o>>=1) sm2+=__shfl_xor_sync(0xffffffffu,sm2,o);
            if((tid&31)==0) redbuf[tid>>5]=sm2;
            __syncthreads();
            float s0h=redbuf[0]+redbuf[1]+redbuf[2]+redbuf[3];
            float s1h=redbuf[4]+redbuf[5]+redbuf[6]+redbuf[7];
            float wc=ex/((tid<128)?s0h:s1h);

            float wprev=(tid<128)?wrp[n]:wwp[n];
            float ggate=(tid<128)?sc[1]:sc[7];
            float wg=ggate*wc+(1.f-ggate)*wprev;
            __syncthreads();
            if(tid<128) wcr[n]=wg; else wcw[n]=wg;
            __syncthreads();

            float sA,sB,sC,gam;
            if(tid<128){sA=sc[2];sB=sc[3];sC=sc[4];gam=sc[5];}
            else       {sA=sc[8];sB=sc[9];sC=sc[10];gam=sc[11];}
            const float* WArr=(tid<128)?wcr:wcw;
            float wsv=sA*WArr[(n+1)&127]+sB*WArr[n]+sC*WArr[(n+127)&127];
            float wp=powf(wsv+EPSF,gam);
            __syncthreads();
            float sp=wp;
#pragma unroll
            for(int o=16;o>0;o>>=1) sp+=__shfl_xor_sync(0xffffffffu,sp,o);
            if((tid&31)==0) redbuf[tid>>5]=sp;
            __syncthreads();
            float p0=redbuf[0]+redbuf[1]+redbuf[2]+redbuf[3];
            float p1=redbuf[4]+redbuf[5]+redbuf[6]+redbuf[7];
            float wfin=wp/((tid<128)?p0:p1);
            if(tid<128){wcr[n]=wfin;wrp[n]=wfin;}
            else       {wcw[n]=wfin;wwp[n]=wfin;}
            __syncthreads();

            for(int i=tid;i<8192;i+=256){
                int n2=i>>6,c=i&63;
                float wwn=wcw[n2];
                float mval=Ms[n2*65+c];
                Ms[n2*65+c]=mval*(1.f-wwn*er[c])+wwn*aw[c];
            }
            __syncthreads();
            if(tid<64){
                int c=tid;
                float acc=0.f;
                for(int n2=0;n2<128;n2++) acc+=wcr[n2]*Ms[n2*65+c];
                d_XT[(512+c)*32+b]=acc;
                d_HR[(t*576+512+c)*32+b]=acc;
            }
            __syncthreads();
        }
        nb++; gridbar(nb*NBLK);
    }
}

__global__ __launch_bounds__(256) void out_gemm_kernel(const float* __restrict__ b_out,
                                                       float* __restrict__ out){
    __shared__ __align__(16) float Ws[32*256];
    __shared__ __align__(16) float Xs[32*32];
    int t=blockIdx.x,tid=threadIdx.x;
    int og=tid>>2,bg=tid&3;
    float acc[8][4]={};
    for(int kc=0;kc<18;kc++){
        for(int idx=tid;idx<32*64;idx+=256){
            int k=idx>>6,o4=idx&63;
            *(float4*)&Ws[k*256+o4*4]=*(const float4*)&d_WoutT[(kc*32+k)*256+o4*4];
        }
        for(int idx=tid;idx<32*8;idx+=256){
            int k=idx>>3,b4=idx&7;
            *(float4*)&Xs[k*32+b4*4]=*(const float4*)&d_HR[(t*576+kc*32+k)*32+b4*4];
        }
        __syncthreads();
#pragma unroll 8
        for(int k=0;k<32;k++){
            float4 wv=*(float4*)&Ws[k*256+og*4];
            float4 x0=*(float4*)&Xs[k*32+bg*8];
            float4 x1=*(float4*)&Xs[k*32+bg*8+4];
            acc[0][0]+=x0.x*wv.x;acc[0][1]+=x0.x*wv.y;acc[0][2]+=x0.x*wv.z;acc[0][3]+=x0.x*wv.w;
            acc[1][0]+=x0.y*wv.x;acc[1][1]+=x0.y*wv.y;acc[1][2]+=x0.y*wv.z;acc[1][3]+=x0.y*wv.w;
            acc[2][0]+=x0.z*wv.x;acc[2][1]+=x0.z*wv.y;acc[2][2]+=x0.z*wv.z;acc[2][3]+=x0.z*wv.w;
            acc[3][0]+=x0.w*wv.x;acc[3][1]+=x0.w*wv.y;acc[3][2]+=x0.w*wv.z;acc[3][3]+=x0.w*wv.w;
            acc[4][0]+=x1.x*wv.x;acc[4][1]+=x1.x*wv.y;acc[4][2]+=x1.x*wv.z;acc[4][3]+=x1.x*wv.w;
            acc[5][0]+=x1.y*wv.x;acc[5][1]+=x1.y*wv.y;acc[5][2]+=x1.y*wv.z;acc[5][3]+=x1.y*wv.w;
            acc[6][0]+=x1.z*wv.x;acc[6][1]+=x1.z*wv.y;acc[6][2]+=x1.z*wv.z;acc[6][3]+=x1.z*wv.w;
            acc[7][0]+=x1.w*wv.x;acc[7][1]+=x1.w*wv.y;acc[7][2]+=x1.w*wv.z;acc[7][3]+=x1.w*wv.w;
        }
        __syncthreads();
    }
    int o0=og*4;
    float4 bias=*(const float4*)&b_out[o0];
#pragma unroll
    for(int bb=0;bb<8;bb++){
        int b=bg*8+bb;
        *(float4*)&out[(b*256+t)*256+o0]=make_float4(acc[bb][0]+bias.x,acc[bb][1]+bias.y,
                                                     acc[bb][2]+bias.z,acc[bb][3]+bias.w);
    }
}

extern "C" void kernel_launch(void* const* d_in, const int* in_sizes, int n_in,
                              void* d_out, int out_size){
    const float* x     =(const float*)d_in[0];
    const float* W_ih  =(const float*)d_in[1];
    const float* W_hh  =(const float*)d_in[2];
    const float* b_lstm=(const float*)d_in[3];
    const float* W_head=(const float*)d_in[4];
    const float* b_head=(const float*)d_in[5];
    const float* W_out =(const float*)d_in[6];
    const float* b_out =(const float*)d_in[7];
    float* out=(float*)d_out;

    static int smem_set=0;
    if(!smem_set){
        cudaFuncSetAttribute(ntm_loop_kernel, cudaFuncAttributeMaxDynamicSharedMemorySize, SMEM_BYTES);
        smem_set=1;
    }

    prep_kernel<<<148,256>>>(W_ih,W_hh,W_head,W_out);
    tin_kernel<<<dim3(8,256),256>>>(x);
    xp_gemm_kernel<<<dim3(16,256),256>>>();
    ntm_loop_kernel<<<NBLK,256,SMEM_BYTES>>>(b_lstm,b_head);
    out_gemm_kernel<<<256,256>>>(b_out,out);
}

// round 16
// speedup vs baseline: 1.1746x; 1.1746x over previous
#include <cuda_runtime.h>
#include <math.h>

#define NBLK 128
#define EPSF 1e-8f

// smem layout (dynamic, one CTA/SM):
//   [0     ,32768) Ws   64x128  (A1 h-part weights, loaded once)
//   [32768 ,40960) Xs   64x32   (A1 activations, per step)
//   [40960 ,74240) Ms   128x65  (persistent M, B CTAs)
//   [74240 ,74752) wr   (persistent)
//   [74752 ,75264) ww   (persistent)
//   [75264 ,79360) Wrs  16x64   (persistent r-slice weights)
//   [79360 ,89600) scratch: A2 gs[512]+rsm[2048] | B1 sred[768] | B2 transients
#define SMEM_BYTES 89600

__device__ float d_XP[256*2048*32];     // [t][row][b]
__device__ float d_XinT[256*256*32];    // [t][i][b]
__device__ float d_WrecT[576*2048];     // [k][row]
__device__ float d_WxT[256*2048];       // [i][row]
__device__ float d_WheadT[512*272];     // [k][o] padded
__device__ float d_WoutT[576*256];      // [k][o]
__device__ float d_Part[8*2048*32];     // [kc][row][b]
__device__ float d_XT[576*32];          // [k][b] 0..511=h, 512..575=r
__device__ float d_cT[512*32];          // [j][b]
__device__ float d_HR[256*576*32];      // [t][k][b]
__device__ float d_P[272*32];           // [o][b]
__device__ unsigned d_barcnt;
__device__ __align__(128) unsigned d_headcnt[32];

__device__ __forceinline__ float sigmf(float x){ return 1.f/(1.f+expf(-x)); }
__device__ __forceinline__ float softplusf(float x){ return fmaxf(x,0.f)+log1pf(expf(-fabsf(x))); }

__device__ __forceinline__ void gridbar(unsigned target){
    __syncthreads();
    __threadfence();
    if(threadIdx.x==0){
        atomicAdd(&d_barcnt,1u);
        while(*(volatile unsigned*)&d_barcnt < target){ __nanosleep(64); }
        __threadfence();
    }
    __syncthreads();
}

__global__ void prep_kernel(const float* __restrict__ W_ih,const float* __restrict__ W_hh,
                            const float* __restrict__ W_head,const float* __restrict__ W_out){
    if(blockIdx.x==0&&threadIdx.x==0){ d_barcnt=0u; d_headcnt[0]=0u; }
    int tid=blockIdx.x*blockDim.x+threadIdx.x, nt=gridDim.x*blockDim.x;
    for(int i=tid;i<576*2048;i+=nt){
        int k=i>>11,row=i&2047;
        d_WrecT[i]=(k<512)?W_hh[row*512+k]:W_ih[row*320+256+(k-512)];
    }
    for(int i=tid;i<256*2048;i+=nt){
        int k=i>>11,row=i&2047;
        d_WxT[i]=W_ih[row*320+k];
    }
    for(int i=tid;i<512*272;i+=nt){
        int j=i/272,o=i%272;
        d_WheadT[i]=(o<268)?W_head[o*512+j]:0.f;
    }
    for(int i=tid;i<576*256;i+=nt){
        int k=i>>8,o=i&255;
        d_WoutT[i]=W_out[o*576+k];
    }
}

__global__ void tin_kernel(const float* __restrict__ x){
    __shared__ float sm[32][33];
    int it=blockIdx.x,t=blockIdx.y;
    int lane=threadIdx.x&31,r=threadIdx.x>>5,i0=it*32;
#pragma unroll
    for(int q=0;q<4;q++){ int b=r+q*8; sm[lane][b]=x[(b*256+t)*256+i0+lane]; }
    __syncthreads();
#pragma unroll
    for(int q=0;q<4;q++){ int i=r+q*8; d_XinT[(t*256+i0+i)*32+lane]=sm[i][lane]; }
}

__global__ __launch_bounds__(256) void xp_gemm_kernel(){
    __shared__ __align__(16) float Ws[64*128];
    __shared__ __align__(16) float Xs[64*32];
    int rb=blockIdx.x,t=blockIdx.y,tid=threadIdx.x;
    int ty=tid>>3,tx=tid&7;
    float acc[4][4]={};
    for(int kc=0;kc<4;kc++){
        for(int idx=tid;idx<64*32;idx+=256){
            int k=idx>>5,r4=idx&31;
            *(float4*)&Ws[k*128+r4*4]=*(const float4*)&d_WxT[(kc*64+k)*2048+rb*128+r4*4];
        }
        for(int idx=tid;idx<64*8;idx+=256){
            int k=idx>>3,b4=idx&7;
            *(float4*)&Xs[k*32+b4*4]=*(const float4*)&d_XinT[(t*256+kc*64+k)*32+b4*4];
        }
        __syncthreads();
#pragma unroll 8
        for(int k=0;k<64;k++){
            float4 wv=*(float4*)&Ws[k*128+ty*4];
            float4 xv=*(float4*)&Xs[k*32+tx*4];
            acc[0][0]+=wv.x*xv.x;acc[0][1]+=wv.x*xv.y;acc[0][2]+=wv.x*xv.z;acc[0][3]+=wv.x*xv.w;
            acc[1][0]+=wv.y*xv.x;acc[1][1]+=wv.y*xv.y;acc[1][2]+=wv.y*xv.z;acc[1][3]+=wv.y*xv.w;
            acc[2][0]+=wv.z*xv.x;acc[2][1]+=wv.z*xv.y;acc[2][2]+=wv.z*xv.z;acc[2][3]+=wv.z*xv.w;
            acc[3][0]+=wv.w*xv.x;acc[3][1]+=wv.w*xv.y;acc[3][2]+=wv.w*xv.z;acc[3][3]+=wv.w*xv.w;
        }
        __syncthreads();
    }
    int row0=rb*128+ty*4;
#pragma unroll
    for(int i=0;i<4;i++)
        *(float4*)&d_XP[(t*2048+row0+i)*32+tx*4]=make_float4(acc[i][0],acc[i][1],acc[i][2],acc[i][3]);
}

__global__ __launch_bounds__(256) void ntm_loop_kernel(const float* __restrict__ b_lstm,
                                                       const float* __restrict__ b_head){
    extern __shared__ __align__(16) char smraw[];
    float* Ws   =(float*)(smraw);           // [64][128]
    float* Xs   =(float*)(smraw+32768);     // [64][32]
    float* Ms   =(float*)(smraw+40960);     // [128][65]
    float* wrp  =(float*)(smraw+74240);
    float* wwp  =(float*)(smraw+74752);
    float* Wrs  =(float*)(smraw+75264);     // [16][64] persistent r-slice
    float* gs   =(float*)(smraw+79360);     // A2: 512
    float* rsm  =(float*)(smraw+81408);     // A2: r staged [c][b] 64x32
    float* sred =(float*)(smraw+79360);     // B1 scratch (768)
    float* ps   =(float*)(smraw+79360);     // B2 transients
    float* kr   =ps+272;
    float* kw   =kr+64;
    float* er   =kw+64;
    float* aw   =er+64;
    float* wcr  =aw+64;
    float* wcw  =wcr+128;
    float* redbuf=wcw+128;
    float* sc   =redbuf+8;
    float* minv =sc+16;

    const int g=blockIdx.x,tid=threadIdx.x;
    unsigned nb=0;
    const int rb=g>>3,kc=g&7;
    const int ty=tid>>3,tx=tid&7;
    const bool isB1=(g>=32&&g<122);
    const bool isB2=(g<32);

    // ---- init ----
    {
        int gt=g*256+tid; const int nt=NBLK*256;
        for(int i=gt;i<576*32;i+=nt) d_XT[i]=0.f;
        for(int i=gt;i<512*32;i+=nt) d_cT[i]=0.f;
        for(int i=gt;i<8*2048*32;i+=nt) d_Part[i]=0.f;
    }
    // persistent A1 weights (h-part, k<512), loaded once
    for(int idx=tid;idx<64*32;idx+=256){
        int k=idx>>5,r4=idx&31;
        *(float4*)&Ws[k*128+r4*4]=*(const float4*)&d_WrecT[(kc*64+k)*2048+rb*128+r4*4];
    }
    // persistent r-slice weights
    for(int i=tid;i<1024;i+=256){
        int lr=i>>6,c=i&63;
        int row=(lr>>2)*512 + g*4 + (lr&3);
        Wrs[i]=d_WrecT[(512+c)*2048+row];
    }
    // persistent NTM state for B CTAs
    if(isB2){
        for(int i=tid;i<8192;i+=256) Ms[(i>>6)*65+(i&63)]=0.01f;
        if(tid<128){ float v=(tid==0)?1.f:0.f; wrp[tid]=v; wwp[tid]=v; }
    }
    nb++; gridbar(nb*NBLK);

    for(int t=0;t<256;t++){
        // ===== A2(t): reduce partials + r-part + XP + bias ; LSTM -> h(t) =====
        {
            for(int i=tid;i<512;i+=256)
                *(float4*)&rsm[i*4]=*(const float4*)&d_XT[512*32+i*4];
            __syncthreads();
            for(int v=tid;v<512;v+=256){
                int q=v>>7,jo=(v>>5)&3,b=v&31;
                int row=q*512+g*4+jo;
                int lr=q*4+jo;
                float s=b_lstm[row]+d_XP[(t*2048+row)*32+b];
#pragma unroll
                for(int kk=0;kk<8;kk++) s+=d_Part[(kk*2048+row)*32+b];
#pragma unroll
                for(int c=0;c<64;c+=4){
                    float4 wv=*(const float4*)&Wrs[lr*64+c];
                    s+=wv.x*rsm[c*32+b]+wv.y*rsm[(c+1)*32+b]
                      +wv.z*rsm[(c+2)*32+b]+wv.w*rsm[(c+3)*32+b];
                }
                gs[v]=s;
            }
            __syncthreads();
            if(tid<128){
                int jo=tid>>5,b=tid&31,j=g*4+jo;
                float gi=gs[jo*32+b];
                float gf=gs[128+jo*32+b];
                float gg=gs[256+jo*32+b];
                float go=gs[384+jo*32+b];
                float c=sigmf(gf)*d_cT[j*32+b]+sigmf(gi)*tanhf(gg);
                float h=sigmf(go)*tanhf(c);
                d_cT[j*32+b]=c;
                d_XT[j*32+b]=h;
                d_HR[(t*576+j)*32+b]=h;
            }
            __syncthreads();
        }
        nb++; gridbar(nb*NBLK);

        // ===== B1(t) FIRST on B1-CTAs (unblocks B2 ~1.2us earlier) =====
        if(isB1){
            int o3=(g-32)*3,kg=tid>>5,b=tid&31;
            float a0=0.f,a1=0.f,a2v=0.f;
            for(int k=kg*64;k<kg*64+64;k++){
                float xv=d_XT[k*32+b];
                a0 +=d_WheadT[k*272+o3  ]*xv;
                a1 +=d_WheadT[k*272+o3+1]*xv;
                a2v+=d_WheadT[k*272+o3+2]*xv;
            }
            sred[kg*96+   b]=a0;
            sred[kg*96+32+b]=a1;
            sred[kg*96+64+b]=a2v;
            __syncthreads();
            if(tid<96){
                int m=tid>>5,bb=tid&31,o=o3+m;
                if(o<268){
                    float s=0.f;
#pragma unroll
                    for(int q=0;q<8;q++) s+=sred[q*96+m*32+bb];
                    d_P[o*32+bb]=s;
                }
            }
            __syncthreads();
            if(tid==0){ __threadfence(); atomicAdd(&d_headcnt[0],1u); }
        }

        // ===== A1(t+1): h-part recurrent GEMM partials (all CTAs) =====
        {
            for(int idx=tid;idx<64*8;idx+=256){
                int k=idx>>3,b4=idx&7;
                *(float4*)&Xs[k*32+b4*4]=*(const float4*)&d_XT[(kc*64+k)*32+b4*4];
            }
            __syncthreads();
            float acc[4][4]={};
#pragma unroll 4
            for(int k=0;k<64;k++){
                float4 wv=*(float4*)&Ws[k*128+ty*4];
                float4 xv=*(float4*)&Xs[k*32+tx*4];
                acc[0][0]+=wv.x*xv.x;acc[0][1]+=wv.x*xv.y;acc[0][2]+=wv.x*xv.z;acc[0][3]+=wv.x*xv.w;
                acc[1][0]+=wv.y*xv.x;acc[1][1]+=wv.y*xv.y;acc[1][2]+=wv.y*xv.z;acc[1][3]+=wv.y*xv.w;
                acc[2][0]+=wv.z*xv.x;acc[2][1]+=wv.z*xv.y;acc[2][2]+=wv.z*xv.z;acc[2][3]+=wv.z*xv.w;
                acc[3][0]+=wv.w*xv.x;acc[3][1]+=wv.w*xv.y;acc[3][2]+=wv.w*xv.z;acc[3][3]+=wv.w*xv.w;
            }
            int row0=rb*128+ty*4;
#pragma unroll
            for(int i=0;i<4;i++)
                *(float4*)&d_Part[(kc*2048+row0+i)*32+tx*4]=make_float4(acc[i][0],acc[i][1],acc[i][2],acc[i][3]);
            __syncthreads();
        }

        // ===== B2(t) (g<32): wait for 90 head producers, then addressing =====
        if(isB2){
            if(tid==0){
                unsigned tgt=90u*(unsigned)(t+1);
                while(*(volatile unsigned*)&d_headcnt[0] < tgt){ __nanosleep(64); }
                __threadfence();
            }
            __syncthreads();
            const int b=g;
            for(int o=tid;o<272;o+=256) ps[o]=(o<268)?(d_P[o*32+b]+b_head[o]):0.f;
            __syncthreads();
            if(tid==0){
                sc[0]=softplusf(ps[64]);
                sc[1]=sigmf(ps[65]);
                float m=fmaxf(ps[66],fmaxf(ps[67],ps[68]));
                float e0=expf(ps[66]-m),e1=expf(ps[67]-m),e2=expf(ps[68]-m);
                float s=e0+e1+e2;
                sc[2]=e0/s;sc[3]=e1/s;sc[4]=e2/s;
                sc[5]=1.f+softplusf(ps[69]);
            }
            if(tid==32){
                sc[6]=softplusf(ps[134]);
                sc[7]=sigmf(ps[135]);
                float m=fmaxf(ps[136],fmaxf(ps[137],ps[138]));
                float e0=expf(ps[136]-m),e1=expf(ps[137]-m),e2=expf(ps[138]-m);
                float s=e0+e1+e2;
                sc[8]=e0/s;sc[9]=e1/s;sc[10]=e2/s;
                sc[11]=1.f+softplusf(ps[139]);
            }
            if(tid==64){
                float s=0.f;
                for(int c=0;c<64;c++){float v=ps[c];s+=v*v;}
                sc[12]=sqrtf(s)+EPSF;
            }
            if(tid==96){
                float s=0.f;
                for(int c=0;c<64;c++){float v=ps[70+c];s+=v*v;}
                sc[13]=sqrtf(s)+EPSF;
            }
            if(tid>=128&&tid<192){
                int c=tid-128;
                kr[c]=ps[c];
                kw[c]=ps[70+c];
                er[c]=sigmf(ps[140+c]);
                aw[c]=ps[204+c];
            }
            __syncthreads();

            const int n=tid&127;
            float myv;
            {
                const float* mr=&Ms[n*65];
                if(tid<128){
                    float m2=0.f,dr=0.f;
                    for(int c=0;c<64;c++){float mv=mr[c];m2+=mv*mv;dr+=mv*kr[c];}
                    float inv=1.f/(sqrtf(m2)+EPSF);
                    minv[n]=inv;
                    myv=sc[0]*dr*inv/sc[12];
                }else{
                    float dw=0.f;
                    for(int c=0;c<64;c++) dw+=mr[c]*kw[c];
                    myv=dw;
                }
            }
            __syncthreads();
            if(tid>=128) myv=sc[6]*myv*minv[n]/sc[13];

            float m=myv;
#pragma unroll
            for(int o=16;o>0;o>>=1) m=fmaxf(m,__shfl_xor_sync(0xffffffffu,m,o));
            if((tid&31)==0) redbuf[tid>>5]=m;
            __syncthreads();
            float h0=fmaxf(fmaxf(redbuf[0],redbuf[1]),fmaxf(redbuf[2],redbuf[3]));
            float h1=fmaxf(fmaxf(redbuf[4],redbuf[5]),fmaxf(redbuf[6],redbuf[7]));
            __syncthreads();
            float ex=expf(myv-((tid<128)?h0:h1));
            float sm2=ex;
#pragma unroll
            for(int o=16;o>0;o>>=1) sm2+=__shfl_xor_sync(0xffffffffu,sm2,o);
            if((tid&31)==0) redbuf[tid>>5]=sm2;
            __syncthreads();
            float s0h=redbuf[0]+redbuf[1]+redbuf[2]+redbuf[3];
            float s1h=redbuf[4]+redbuf[5]+redbuf[6]+redbuf[7];
            float wc=ex/((tid<128)?s0h:s1h);

            float wprev=(tid<128)?wrp[n]:wwp[n];
            float ggate=(tid<128)?sc[1]:sc[7];
            float wg=ggate*wc+(1.f-ggate)*wprev;
            __syncthreads();
            if(tid<128) wcr[n]=wg; else wcw[n]=wg;
            __syncthreads();

            float sA,sB,sC,gam;
            if(tid<128){sA=sc[2];sB=sc[3];sC=sc[4];gam=sc[5];}
            else       {sA=sc[8];sB=sc[9];sC=sc[10];gam=sc[11];}
            const float* WArr=(tid<128)?wcr:wcw;
            float wsv=sA*WArr[(n+1)&127]+sB*WArr[n]+sC*WArr[(n+127)&127];
            float wp=powf(wsv+EPSF,gam);
            __syncthreads();
            float sp=wp;
#pragma unroll
            for(int o=16;o>0;o>>=1) sp+=__shfl_xor_sync(0xffffffffu,sp,o);
            if((tid&31)==0) redbuf[tid>>5]=sp;
            __syncthreads();
            float p0=redbuf[0]+redbuf[1]+redbuf[2]+redbuf[3];
            float p1=redbuf[4]+redbuf[5]+redbuf[6]+redbuf[7];
            float wfin=wp/((tid<128)?p0:p1);
            if(tid<128){wcr[n]=wfin;wrp[n]=wfin;}
            else       {wcw[n]=wfin;wwp[n]=wfin;}
            __syncthreads();

            for(int i=tid;i<8192;i+=256){
                int n2=i>>6,c=i&63;
                float wwn=wcw[n2];
                float mval=Ms[n2*65+c];
                Ms[n2*65+c]=mval*(1.f-wwn*er[c])+wwn*aw[c];
            }
            __syncthreads();
            if(tid<64){
                int c=tid;
                float acc=0.f;
                for(int n2=0;n2<128;n2++) acc+=wcr[n2]*Ms[n2*65+c];
                d_XT[(512+c)*32+b]=acc;
                d_HR[(t*576+512+c)*32+b]=acc;
            }
            __syncthreads();
        }
        nb++; gridbar(nb*NBLK);
    }
}

__global__ __launch_bounds__(256) void out_gemm_kernel(const float* __restrict__ b_out,
                                                       float* __restrict__ out){
    __shared__ __align__(16) float Ws[32*256];
    __shared__ __align__(16) float Xs[32*32];
    int t=blockIdx.x,tid=threadIdx.x;
    int og=tid>>2,bg=tid&3;
    float acc[8][4]={};
    for(int kc=0;kc<18;kc++){
        for(int idx=tid;idx<32*64;idx+=256){
            int k=idx>>6,o4=idx&63;
            *(float4*)&Ws[k*256+o4*4]=*(const float4*)&d_WoutT[(kc*32+k)*256+o4*4];
        }
        for(int idx=tid;idx<32*8;idx+=256){
            int k=idx>>3,b4=idx&7;
            *(float4*)&Xs[k*32+b4*4]=*(const float4*)&d_HR[(t*576+kc*32+k)*32+b4*4];
        }
        __syncthreads();
#pragma unroll 8
        for(int k=0;k<32;k++){
            float4 wv=*(float4*)&Ws[k*256+og*4];
            float4 x0=*(float4*)&Xs[k*32+bg*8];
            float4 x1=*(float4*)&Xs[k*32+bg*8+4];
            acc[0][0]+=x0.x*wv.x;acc[0][1]+=x0.x*wv.y;acc[0][2]+=x0.x*wv.z;acc[0][3]+=x0.x*wv.w;
            acc[1][0]+=x0.y*wv.x;acc[1][1]+=x0.y*wv.y;acc[1][2]+=x0.y*wv.z;acc[1][3]+=x0.y*wv.w;
            acc[2][0]+=x0.z*wv.x;acc[2][1]+=x0.z*wv.y;acc[2][2]+=x0.z*wv.z;acc[2][3]+=x0.z*wv.w;
            acc[3][0]+=x0.w*wv.x;acc[3][1]+=x0.w*wv.y;acc[3][2]+=x0.w*wv.z;acc[3][3]+=x0.w*wv.w;
            acc[4][0]+=x1.x*wv.x;acc[4][1]+=x1.x*wv.y;acc[4][2]+=x1.x*wv.z;acc[4][3]+=x1.x*wv.w;
            acc[5][0]+=x1.y*wv.x;acc[5][1]+=x1.y*wv.y;acc[5][2]+=x1.y*wv.z;acc[5][3]+=x1.y*wv.w;
            acc[6][0]+=x1.z*wv.x;acc[6][1]+=x1.z*wv.y;acc[6][2]+=x1.z*wv.z;acc[6][3]+=x1.z*wv.w;
            acc[7][0]+=x1.w*wv.x;acc[7][1]+=x1.w*wv.y;acc[7][2]+=x1.w*wv.z;acc[7][3]+=x1.w*wv.w;
        }
        __syncthreads();
    }
    int o0=og*4;
    float4 bias=*(const float4*)&b_out[o0];
#pragma unroll
    for(int bb=0;bb<8;bb++){
        int b=bg*8+bb;
        *(float4*)&out[(b*256+t)*256+o0]=make_float4(acc[bb][0]+bias.x,acc[bb][1]+bias.y,
                                                     acc[bb][2]+bias.z,acc[bb][3]+bias.w);
    }
}

extern "C" void kernel_launch(void* const* d_in, const int* in_sizes, int n_in,
                              void* d_out, int out_size){
    const float* x     =(const float*)d_in[0];
    const float* W_ih  =(const float*)d_in[1];
    const float* W_hh  =(const float*)d_in[2];
    const float* b_lstm=(const float*)d_in[3];
    const float* W_head=(const float*)d_in[4];
    const float* b_head=(const float*)d_in[5];
    const float* W_out =(const float*)d_in[6];
    const float* b_out =(const float*)d_in[7];
    float* out=(float*)d_out;

    static int smem_set=0;
    if(!smem_set){
        cudaFuncSetAttribute(ntm_loop_kernel, cudaFuncAttributeMaxDynamicSharedMemorySize, SMEM_BYTES);
        smem_set=1;
    }

    prep_kernel<<<148,256>>>(W_ih,W_hh,W_head,W_out);
    tin_kernel<<<dim3(8,256),256>>>(x);
    xp_gemm_kernel<<<dim3(16,256),256>>>();
    ntm_loop_kernel<<<NBLK,256,SMEM_BYTES>>>(b_lstm,b_head);
    out_gemm_kernel<<<256,256>>>(b_out,out);
}